// round 4
// baseline (speedup 1.0000x reference)
#include <cuda_runtime.h>
#include <cstdint>

// ---------------- problem constants ----------------
#define CIN   128
#define COUT  256
#define DTOT  1152
#define RCH   18            // 18 chunks of K=64
#define NTH   512

#define A_STRIDE 72                     // 64 data bytes + 8 pad (bank spread)
#define A_PLANE  (128 * A_STRIDE)       // 9216 B per s8 plane
#define B_OFF    (3 * A_PLANE)          // 27648
#define STAGE    (B_OFF + 128 * A_STRIDE)  // 36864 B per stage
#define SMEM_TOTAL (2 * STAGE)          // 73728 B

// ---------------- device scratch ----------------
__device__ unsigned g_mm[2];                               // enc(max w), enc(max -w)
__device__ __align__(16) signed char g_wq[RCH * COUT * 64]; // s8 W [r][m][k]

// ---------------- helpers ----------------
__device__ __forceinline__ unsigned encf(float f) {
    int b = __float_as_int(f);
    return (b < 0) ? ~(unsigned)b : ((unsigned)b | 0x80000000u);
}
__device__ __forceinline__ float decf(unsigned u) {
    int b = (u & 0x80000000u) ? (int)(u & 0x7fffffffu) : ~(int)u;
    return __int_as_float(b);
}

__device__ __forceinline__ void imma(int* d, const unsigned* a, const unsigned* b) {
    asm volatile(
        "mma.sync.aligned.m16n8k32.row.col.s32.s8.s8.s32 "
        "{%0,%1,%2,%3}, {%4,%5,%6,%7}, {%8,%9}, {%0,%1,%2,%3};"
        : "+r"(d[0]), "+r"(d[1]), "+r"(d[2]), "+r"(d[3])
        : "r"(a[0]), "r"(a[1]), "r"(a[2]), "r"(a[3]),
          "r"(b[0]), "r"(b[1]));
}

// ---------------- pre-kernels ----------------
__global__ void k_init_mm() { if (threadIdx.x < 2) g_mm[threadIdx.x] = 0u; }

__global__ void k_minmax(const float* __restrict__ w, int n) {
    unsigned mx = 0u, mn = 0u;
    for (int i = blockIdx.x * blockDim.x + threadIdx.x; i < n;
         i += gridDim.x * blockDim.x) {
        float f = w[i];
        unsigned e0 = encf(f), e1 = encf(-f);
        mx = mx > e0 ? mx : e0;
        mn = mn > e1 ? mn : e1;
    }
    #pragma unroll
    for (int o = 16; o; o >>= 1) {
        unsigned a = __shfl_xor_sync(0xffffffffu, mx, o);
        unsigned b = __shfl_xor_sync(0xffffffffu, mn, o);
        mx = mx > a ? mx : a;
        mn = mn > b ? mn : b;
    }
    if ((threadIdx.x & 31) == 0) {
        atomicMax(&g_mm[0], mx);
        atomicMax(&g_mm[1], mn);
    }
}

// quantize to s8, layout [chunk r][m 256][k 64]
__global__ void k_quant(const float* __restrict__ w) {
    int idx = blockIdx.x * blockDim.x + threadIdx.x;
    if (idx >= COUT * DTOT) return;
    float mx = decf(g_mm[0]);
    float mn = -decf(g_mm[1]);
    float scale = 15.0f / (mx - mn + 1e-9f);
    int m = idx / DTOT;
    int d = idx - m * DTOT;
    float q = fminf(fmaxf(rintf(w[idx] * scale), -7.0f), 7.0f);
    int r = d >> 6, kk = d & 63;
    g_wq[(r * COUT + m) * 64 + kk] = (signed char)(int)q;
}

// ---------------- main kernel ----------------
__global__ __launch_bounds__(NTH, 1)
void k_onn_main(const float* __restrict__ inp, float* __restrict__ out) {
    extern __shared__ __align__(16) unsigned char smem[];
    const int tid  = threadIdx.x;
    const int lane = tid & 31;
    const int wid  = tid >> 5;
    const int wm = wid & 3;         // pixel 32-group
    const int wn = wid >> 2;        // channel 32-group

    const int bx = blockIdx.x;      // 0..255
    const int b  = bx >> 4;
    const int pb = (bx >> 1) & 7;
    const int h  = bx & 1;
    const int pixbase = pb * 128;
    const int y0 = pb * 4;
    const int chbase = h * 128;

    const float* __restrict__ inb = inp + (size_t)b * (CIN * 1024);

    // producer mapping: thread -> (pixel pp, base k-group pkg)
    const int pp  = tid >> 2;        // 0..127
    const int pkg = tid & 3;
    const int py  = y0 + (pp >> 5);
    const int px  = pp & 31;

    // ---- prologue: fill stage 0 with chunk 0 ----
    {
        unsigned char* Ad = smem;
        #pragma unroll
        for (int i = 0; i < 4; i++) {
            const int kg = pkg + 4 * i;
            unsigned wh = 0, wmid = 0, wlo = 0;
            #pragma unroll
            for (int j = 0; j < 4; j++) {
                const int d  = kg * 4 + j;            // chunk 0
                const int c  = d / 9;
                const int e  = d - 9 * c;
                const int dy = e / 3 - 1;
                const int dx = e - 3 * (e / 3) - 1;
                const int yy = py + dy, xx = px + dx;
                float v = 0.0f;
                if ((unsigned)yy < 32u && (unsigned)xx < 32u)
                    v = inb[c * 1024 + yy * 32 + xx];
                int vi = __float2int_rn(v * 524288.0f);
                int lo = (vi << 24) >> 24;
                int t1 = (vi - lo) >> 8;
                int mi = (t1 << 24) >> 24;
                int hi = (t1 - mi) >> 8;
                wh   |= ((unsigned)hi & 255u) << (8 * j);
                wmid |= ((unsigned)mi & 255u) << (8 * j);
                wlo  |= ((unsigned)lo & 255u) << (8 * j);
            }
            const int off = pp * A_STRIDE + kg * 4;
            *(unsigned*)(Ad + off)               = wh;
            *(unsigned*)(Ad + A_PLANE + off)     = wmid;
            *(unsigned*)(Ad + 2 * A_PLANE + off) = wlo;
        }
        const unsigned* gB = (const unsigned*)(g_wq + chbase * 64);
        #pragma unroll
        for (int i = 0; i < 4; i++) {
            const int w = tid + i * 512;
            *(unsigned*)(Ad + B_OFF + (w >> 4) * A_STRIDE + (w & 15) * 4) = gB[w];
        }
    }

    unsigned cnt[8];
    #pragma unroll
    for (int t = 0; t < 8; t++) cnt[t] = 0u;

    for (int r = 0; r < RCH; r++) {
        const int s = r & 1;
        __syncthreads();            // stage s ready; stage s^1 free

        // ---- early global loads for chunk r+1 ----
        float xv[16];
        unsigned bw[4];
        const int rn = r + 1;
        if (rn < RCH) {
            #pragma unroll
            for (int i = 0; i < 4; i++)
                #pragma unroll
                for (int j = 0; j < 4; j++) {
                    const int d  = rn * 64 + (pkg + 4 * i) * 4 + j;
                    const int c  = d / 9;
                    const int e  = d - 9 * c;
                    const int dy = e / 3 - 1;
                    const int dx = e - 3 * (e / 3) - 1;
                    const int yy = py + dy, xx = px + dx;
                    float v = 0.0f;
                    if ((unsigned)yy < 32u && (unsigned)xx < 32u)
                        v = inb[c * 1024 + yy * 32 + xx];
                    xv[i * 4 + j] = v;
                }
            const unsigned* gB =
                (const unsigned*)(g_wq + rn * 16384 + chbase * 64);
            #pragma unroll
            for (int i = 0; i < 4; i++) bw[i] = gB[tid + i * 512];
        }

        // ---- consume stage s ----
        const unsigned char* As = smem + s * STAGE;
        const unsigned char* Bs = As + B_OFF;

        unsigned bf[4][2][2];
        #pragma unroll
        for (int nt = 0; nt < 4; nt++)
            #pragma unroll
            for (int ks = 0; ks < 2; ks++)
                #pragma unroll
                for (int q = 0; q < 2; q++) {
                    const int n = wn * 32 + nt * 8 + (lane >> 2);
                    bf[nt][ks][q] = *(const unsigned*)
                        (Bs + n * A_STRIDE + ks * 32 + q * 16 + (lane & 3) * 4);
                }

        int acc[8][4];
        #pragma unroll
        for (int t = 0; t < 8; t++)
            #pragma unroll
            for (int q = 0; q < 4; q++) acc[t][q] = 0;

        #pragma unroll
        for (int pl = 0; pl < 3; pl++) {     // hi, mid, lo
            if (pl) {
                #pragma unroll
                for (int t = 0; t < 8; t++)
                    #pragma unroll
                    for (int q = 0; q < 4; q++) acc[t][q] <<= 8;
            }
            unsigned af[2][2][4];
            #pragma unroll
            for (int mt = 0; mt < 2; mt++)
                #pragma unroll
                for (int ks = 0; ks < 2; ks++)
                    #pragma unroll
                    for (int q = 0; q < 4; q++) {
                        const int row = wm * 32 + mt * 16 + (lane >> 2) + (q & 1) * 8;
                        const int kb  = ks * 32 + (q >> 1) * 16 + (lane & 3) * 4;
                        af[mt][ks][q] = *(const unsigned*)
                            (As + pl * A_PLANE + row * A_STRIDE + kb);
                    }
            #pragma unroll
            for (int mt = 0; mt < 2; mt++)
                #pragma unroll
                for (int nt = 0; nt < 4; nt++) {
                    imma(acc[mt * 4 + nt], af[mt][0], bf[nt][0]);
                    imma(acc[mt * 4 + nt], af[mt][1], bf[nt][1]);
                }
        }

        // ---- binarize + packed count ----
        #pragma unroll
        for (int t = 0; t < 8; t++) {
            unsigned inc = ((unsigned)(~acc[t][0]) >> 31)
                         | (((unsigned)(~acc[t][1]) >> 31) << 8)
                         | (((unsigned)(~acc[t][2]) >> 31) << 16)
                         | (((unsigned)(~acc[t][3]) >> 31) << 24);
            cnt[t] += inc;
        }

        // ---- split + store chunk r+1 into stage s^1 ----
        if (rn < RCH) {
            unsigned char* Ad = smem + (s ^ 1) * STAGE;
            #pragma unroll
            for (int i = 0; i < 4; i++) {
                unsigned wh = 0, wmid = 0, wlo = 0;
                #pragma unroll
                for (int j = 0; j < 4; j++) {
                    int vi = __float2int_rn(xv[i * 4 + j] * 524288.0f);
                    int lo = (vi << 24) >> 24;
                    int t1 = (vi - lo) >> 8;
                    int mi = (t1 << 24) >> 24;
                    int hi = (t1 - mi) >> 8;
                    wh   |= ((unsigned)hi & 255u) << (8 * j);
                    wmid |= ((unsigned)mi & 255u) << (8 * j);
                    wlo  |= ((unsigned)lo & 255u) << (8 * j);
                }
                const int kg  = pkg + 4 * i;
                const int off = pp * A_STRIDE + kg * 4;
                *(unsigned*)(Ad + off)               = wh;
                *(unsigned*)(Ad + A_PLANE + off)     = wmid;
                *(unsigned*)(Ad + 2 * A_PLANE + off) = wlo;
            }
            #pragma unroll
            for (int i = 0; i < 4; i++) {
                const int w = tid + i * 512;
                *(unsigned*)(Ad + B_OFF + (w >> 4) * A_STRIDE + (w & 15) * 4) = bw[i];
            }
        }
    }

    // ---- coalesced store via warp shuffle transpose ----
    float* __restrict__ ob =
        out + (size_t)b * (COUT * 1024) + (size_t)chbase * 1024 + pixbase;
    #pragma unroll
    for (int nt = 0; nt < 4; nt++) {
        const unsigned va = cnt[nt];        // mt = 0 tiles
        const unsigned vb = cnt[4 + nt];    // mt = 1 tiles
        #pragma unroll
        for (int c8 = 0; c8 < 8; c8++) {
            const int src = ((lane & 7) << 2) + (c8 >> 1);
            unsigned sa = __shfl_sync(0xffffffffu, va, src);
            unsigned sb = __shfl_sync(0xffffffffu, vb, src);
            unsigned v  = (lane & 16) ? sb : sa;
            const int byte = ((lane >> 3) & 1) * 2 + (c8 & 1);
            const float fv = (float)((v >> (byte * 8)) & 255u);
            ob[(size_t)(wn * 32 + nt * 8 + c8) * 1024 + wm * 32 + lane] = fv;
        }
    }
}

// ---------------- launcher ----------------
extern "C" void kernel_launch(void* const* d_in, const int* in_sizes, int n_in,
                              void* d_out, int out_size) {
    const float* inp    = (const float*)d_in[0];  // [16,128,32,32]
    const float* weight = (const float*)d_in[1];  // [256,128,3,3]
    float* out          = (float*)d_out;          // [16,256,32,32]

    const int nw = COUT * DTOT;

    cudaFuncSetAttribute(k_onn_main,
                         cudaFuncAttributeMaxDynamicSharedMemorySize, SMEM_TOTAL);

    k_init_mm<<<1, 32>>>();
    k_minmax<<<256, 256>>>(weight, nw);
    k_quant<<<(nw + 255) / 256, 256>>>(weight);
    k_onn_main<<<256, NTH, SMEM_TOTAL>>>(inp, out);
}

// round 5
// speedup vs baseline: 1.2700x; 1.2700x over previous
#include <cuda_runtime.h>
#include <cstdint>

// ---------------- problem constants ----------------
#define CIN   128
#define COUT  256
#define DTOT  1152
#define RCH   18
#define NTH   640            // 512 consumer + 128 producer threads

#define A_STRIDE 68                     // conflict-free for STS & frag LDS
#define A_PLANE  (128 * A_STRIDE)       // 8704
#define B_STRIDE 72
#define B_OFF    (3 * A_PLANE)          // 26112 (planes: hi, mid, lo)
#define STAGE    (B_OFF + 128 * B_STRIDE)  // 35328
#define CTAB_OFF (2 * STAGE)            // 70656
#define BAR_OFF  (CTAB_OFF + DTOT * 4)  // 75264
#define SMEM_TOTAL (BAR_OFF + 64)
// barriers: full[s] at BAR_OFF + s*8 ; empty[s] at BAR_OFF + 16 + s*8

// ---------------- device scratch ----------------
__device__ unsigned g_mm[2];
__device__ __align__(16) signed char g_wq[RCH * COUT * 64]; // s8 W [r][m][k]

// ---------------- helpers ----------------
__device__ __forceinline__ unsigned encf(float f) {
    int b = __float_as_int(f);
    return (b < 0) ? ~(unsigned)b : ((unsigned)b | 0x80000000u);
}
__device__ __forceinline__ float decf(unsigned u) {
    int b = (u & 0x80000000u) ? (int)(u & 0x7fffffffu) : ~(int)u;
    return __int_as_float(b);
}
__device__ __forceinline__ uint32_t smem_u32(const void* p) {
    uint32_t a;
    asm("{ .reg .u64 t; cvta.to.shared.u64 t, %1; cvt.u32.u64 %0, t; }"
        : "=r"(a) : "l"(p));
    return a;
}
__device__ __forceinline__ void imma(int* d, const unsigned* a, const unsigned* b) {
    asm volatile(
        "mma.sync.aligned.m16n8k32.row.col.s32.s8.s8.s32 "
        "{%0,%1,%2,%3}, {%4,%5,%6,%7}, {%8,%9}, {%0,%1,%2,%3};"
        : "+r"(d[0]), "+r"(d[1]), "+r"(d[2]), "+r"(d[3])
        : "r"(a[0]), "r"(a[1]), "r"(a[2]), "r"(a[3]),
          "r"(b[0]), "r"(b[1]));
}

#define MBAR_INIT(a, c) \
    asm volatile("mbarrier.init.shared.b64 [%0], %1;" :: "r"(a), "r"((uint32_t)(c)) : "memory")
#define MBAR_ARRIVE(a) \
    asm volatile("mbarrier.arrive.shared.b64 _, [%0];" :: "r"(a) : "memory")
#define MBAR_WAIT(a, ph) do {                                                   \
    uint32_t _m = (a); uint32_t _p = (ph); uint32_t _d;                         \
    asm volatile("{\n\t.reg .pred p;\n\t"                                       \
        "mbarrier.try_wait.parity.shared.b64 p, [%1], %2;\n\t"                  \
        "selp.b32 %0, 1, 0, p;\n\t}" : "=r"(_d) : "r"(_m), "r"(_p) : "memory"); \
    if (!_d) {                                                                  \
        asm volatile("{\n\t.reg .pred P1;\n\t"                                  \
        "W_%=:\n\t"                                                             \
        "mbarrier.try_wait.parity.shared.b64 P1, [%0], %1;\n\t"                 \
        "@P1 bra.uni D_%=;\n\t"                                                 \
        "bra.uni W_%=;\n\t"                                                     \
        "D_%=:\n\t}" :: "r"(_m), "r"(_p) : "memory");                           \
    }                                                                           \
} while (0)
#define CP_ASYNC8(dst, src) \
    asm volatile("cp.async.ca.shared.global [%0], [%1], 8;" :: "r"(dst), "l"(src))
#define CP_COMMIT() asm volatile("cp.async.commit_group;" ::: "memory")
#define CP_WAIT0()  asm volatile("cp.async.wait_group 0;" ::: "memory")

// ---------------- pre-kernels ----------------
__global__ void k_init_mm() { if (threadIdx.x < 2) g_mm[threadIdx.x] = 0u; }

__global__ void k_minmax(const float* __restrict__ w, int n) {
    unsigned mx = 0u, mn = 0u;
    for (int i = blockIdx.x * blockDim.x + threadIdx.x; i < n;
         i += gridDim.x * blockDim.x) {
        float f = w[i];
        unsigned e0 = encf(f), e1 = encf(-f);
        mx = mx > e0 ? mx : e0;
        mn = mn > e1 ? mn : e1;
    }
    #pragma unroll
    for (int o = 16; o; o >>= 1) {
        unsigned a = __shfl_xor_sync(0xffffffffu, mx, o);
        unsigned b = __shfl_xor_sync(0xffffffffu, mn, o);
        mx = mx > a ? mx : a;
        mn = mn > b ? mn : b;
    }
    if ((threadIdx.x & 31) == 0) {
        atomicMax(&g_mm[0], mx);
        atomicMax(&g_mm[1], mn);
    }
}

__global__ void k_quant(const float* __restrict__ w) {
    int idx = blockIdx.x * blockDim.x + threadIdx.x;
    if (idx >= COUT * DTOT) return;
    float mx = decf(g_mm[0]);
    float mn = -decf(g_mm[1]);
    float scale = 15.0f / (mx - mn + 1e-9f);
    int m = idx / DTOT;
    int d = idx - m * DTOT;
    float q = fminf(fmaxf(rintf(w[idx] * scale), -7.0f), 7.0f);
    int r = d >> 6, kk = d & 63;
    g_wq[(r * COUT + m) * 64 + kk] = (signed char)(int)q;
}

// ---------------- main kernel: warp-specialized ----------------
__global__ __launch_bounds__(NTH, 1)
void k_onn_main(const float* __restrict__ inp, float* __restrict__ out) {
    extern __shared__ __align__(16) unsigned char smem[];
    const uint32_t sb = smem_u32(smem);
    const int tid  = threadIdx.x;
    const int lane = tid & 31;

    const int bx = blockIdx.x;
    const int b  = bx >> 4;
    const int pb = (bx >> 1) & 7;
    const int h  = bx & 1;
    const int pixbase = pb * 128;
    const int y0 = pb * 4;
    const int chbase = h * 128;

    const float* __restrict__ inb = inp + (size_t)b * (CIN * 1024);
    int* __restrict__ ctab = (int*)(smem + CTAB_OFF);

    // decode table: d -> (c<<8)|(dy<<4)|dx  (dy,dx in 0..2)
    for (int i = tid; i < DTOT; i += NTH) {
        int c = i / 9, e = i - 9 * c;
        int dy = e / 3, dx = e - 3 * dy;
        ctab[i] = (c << 8) | (dy << 4) | dx;
    }
    if (tid == 0) {
        MBAR_INIT(sb + BAR_OFF + 0, 128);   // full[0]
        MBAR_INIT(sb + BAR_OFF + 8, 128);   // full[1]
        MBAR_INIT(sb + BAR_OFF + 16, 512);  // empty[0]
        MBAR_INIT(sb + BAR_OFF + 24, 512);  // empty[1]
    }
    __syncthreads();

    if (tid < 512) {
        // =================== consumers: 16 warps ===================
        const int wid = tid >> 5;
        const int wm  = wid & 3;
        const int wn  = wid >> 2;
        int phf0 = 0, phf1 = 0;

        unsigned cnt[8];
        #pragma unroll
        for (int t = 0; t < 8; t++) cnt[t] = 0u;

        for (int r = 0; r < RCH; r++) {
            const int s = r & 1;
            MBAR_WAIT(sb + BAR_OFF + s * 8, (s ? phf1 : phf0));
            if (s) phf1 ^= 1; else phf0 ^= 1;

            const unsigned char* As = smem + s * STAGE;
            const unsigned char* Bs = As + B_OFF;

            unsigned bf[4][2][2];
            #pragma unroll
            for (int nt = 0; nt < 4; nt++)
                #pragma unroll
                for (int ks = 0; ks < 2; ks++)
                    #pragma unroll
                    for (int q = 0; q < 2; q++) {
                        const int n = wn * 32 + nt * 8 + (lane >> 2);
                        bf[nt][ks][q] = *(const unsigned*)
                            (Bs + n * B_STRIDE + ks * 32 + q * 16 + (lane & 3) * 4);
                    }

            int acc[8][4];
            #pragma unroll
            for (int t = 0; t < 8; t++)
                #pragma unroll
                for (int q = 0; q < 4; q++) acc[t][q] = 0;

            #pragma unroll
            for (int pl = 0; pl < 2; pl++) {          // hi, mid
                if (pl) {
                    #pragma unroll
                    for (int t = 0; t < 8; t++)
                        #pragma unroll
                        for (int q = 0; q < 4; q++) acc[t][q] <<= 8;
                }
                unsigned af[2][2][4];
                #pragma unroll
                for (int mt = 0; mt < 2; mt++)
                    #pragma unroll
                    for (int ks = 0; ks < 2; ks++)
                        #pragma unroll
                        for (int q = 0; q < 4; q++) {
                            const int row = wm * 32 + mt * 16 + (lane >> 2) + (q & 1) * 8;
                            const int kb  = ks * 32 + (q >> 1) * 16 + (lane & 3) * 4;
                            af[mt][ks][q] = *(const unsigned*)
                                (As + pl * A_PLANE + row * A_STRIDE + kb);
                        }
                #pragma unroll
                for (int mt = 0; mt < 2; mt++)
                    #pragma unroll
                    for (int nt = 0; nt < 4; nt++) {
                        imma(acc[mt * 4 + nt], af[mt][0], bf[nt][0]);
                        imma(acc[mt * 4 + nt], af[mt][1], bf[nt][1]);
                    }
            }

            // ---- binarize + exact lo-plane fixup for |S_hm| <= 224 ----
            #pragma unroll
            for (int t = 0; t < 8; t++) {
                const int mt = t >> 2, nt = t & 3;
                unsigned inc = 0, cand = 0;
                #pragma unroll
                for (int q = 0; q < 4; q++) {
                    int v = acc[t][q];
                    inc  |= ((unsigned)(~v) >> 31) << (8 * q);
                    cand |= ((unsigned)(v + 224) <= 448u) ? (1u << q) : 0u;
                }
                if (__any_sync(0xffffffffu, cand)) {
                    #pragma unroll
                    for (int q = 0; q < 4; q++) {
                        if (__any_sync(0xffffffffu, (cand >> q) & 1u)) {
                            if ((cand >> q) & 1u) {
                                const int row = wm * 32 + mt * 16 + (lane >> 2)
                                              + ((q & 2) ? 8 : 0);
                                const int col = wn * 32 + nt * 8 + 2 * (lane & 3)
                                              + (q & 1);
                                const int* xl = (const int*)
                                    (As + 2 * A_PLANE + row * A_STRIDE);
                                const int* wc = (const int*)(Bs + col * B_STRIDE);
                                int slo = 0;
                                #pragma unroll
                                for (int kk = 0; kk < 16; kk++)
                                    slo = __dp4a(xl[kk], wc[kk], slo);
                                int S = (acc[t][q] << 8) + slo;
                                unsigned ob = (unsigned)(~acc[t][q]) >> 31;
                                unsigned nb = (unsigned)(~S) >> 31;
                                inc ^= (ob ^ nb) << (8 * q);
                            }
                        }
                    }
                }
                cnt[t] += inc;
            }
            MBAR_ARRIVE(sb + BAR_OFF + 16 + s * 8);
        }

        // ---- coalesced store via warp shuffle transpose ----
        float* __restrict__ ob =
            out + (size_t)b * (COUT * 1024) + (size_t)chbase * 1024 + pixbase;
        #pragma unroll
        for (int nt = 0; nt < 4; nt++) {
            const unsigned va = cnt[nt];
            const unsigned vb = cnt[4 + nt];
            #pragma unroll
            for (int c8 = 0; c8 < 8; c8++) {
                const int src = ((lane & 7) << 2) + (c8 >> 1);
                unsigned sa = __shfl_sync(0xffffffffu, va, src);
                unsigned sx = __shfl_sync(0xffffffffu, vb, src);
                unsigned v  = (lane & 16) ? sx : sa;
                const int byte = ((lane >> 3) & 1) * 2 + (c8 & 1);
                const float fv = (float)((v >> (byte * 8)) & 255u);
                ob[(size_t)(wn * 32 + nt * 8 + c8) * 1024 + wm * 32 + lane] = fv;
            }
        }
    } else {
        // =================== producers: 4 warps ===================
        const int pp = tid - 512;           // 0..127 = pixel row in tile
        const int py = y0 + (pp >> 5);
        const int px = pp & 31;
        int phe0 = 1, phe1 = 1;

        for (int p = 0; p < RCH; p++) {
            const int s = p & 1;
            MBAR_WAIT(sb + BAR_OFF + 16 + s * 8, (s ? phe1 : phe0));
            if (s) phe1 ^= 1; else phe0 ^= 1;

            unsigned char* Ad = smem + s * STAGE;

            // B tile: 8 x 8B cp.async per thread (row pp)
            {
                const unsigned char* src =
                    (const unsigned char*)g_wq + ((size_t)p * COUT + chbase + pp) * 64;
                const uint32_t dst = sb + s * STAGE + B_OFF + pp * B_STRIDE;
                #pragma unroll
                for (int k8 = 0; k8 < 8; k8++)
                    CP_ASYNC8(dst + k8 * 8, src + k8 * 8);
                CP_COMMIT();
            }

            // A: gather 64 fp32, split to 3 s8 planes; two halves for MLP
            #pragma unroll
            for (int half = 0; half < 2; half++) {
                float v[32];
                #pragma unroll
                for (int i = 0; i < 32; i++) {
                    const int e  = ctab[p * 64 + half * 32 + i];
                    const int yy = py + ((e >> 4) & 15) - 1;
                    const int xx = px + (e & 15) - 1;
                    v[i] = ((unsigned)yy < 32u && (unsigned)xx < 32u)
                             ? inb[((e >> 8) << 10) + yy * 32 + xx] : 0.0f;
                }
                #pragma unroll
                for (int g = 0; g < 8; g++) {
                    unsigned wh = 0, wmd = 0, wl = 0;
                    #pragma unroll
                    for (int j = 0; j < 4; j++) {
                        int vi = __float2int_rn(v[g * 4 + j] * 524288.0f);
                        int lo = (vi << 24) >> 24;
                        int t1 = (vi - lo) >> 8;
                        int mi = (t1 << 24) >> 24;
                        int hi = (t1 - mi) >> 8;
                        wh  |= ((unsigned)hi & 255u) << (8 * j);
                        wmd |= ((unsigned)mi & 255u) << (8 * j);
                        wl  |= ((unsigned)lo & 255u) << (8 * j);
                    }
                    const int off = pp * A_STRIDE + (half * 8 + g) * 4;
                    *(unsigned*)(Ad + off)               = wh;
                    *(unsigned*)(Ad + A_PLANE + off)     = wmd;
                    *(unsigned*)(Ad + 2 * A_PLANE + off) = wl;
                }
            }
            CP_WAIT0();
            MBAR_ARRIVE(sb + BAR_OFF + s * 8);
        }
    }
}

// ---------------- launcher ----------------
extern "C" void kernel_launch(void* const* d_in, const int* in_sizes, int n_in,
                              void* d_out, int out_size) {
    const float* inp    = (const float*)d_in[0];  // [16,128,32,32]
    const float* weight = (const float*)d_in[1];  // [256,128,3,3]
    float* out          = (float*)d_out;          // [16,256,32,32]

    const int nw = COUT * DTOT;

    cudaFuncSetAttribute(k_onn_main,
                         cudaFuncAttributeMaxDynamicSharedMemorySize, SMEM_TOTAL);

    k_init_mm<<<1, 32>>>();
    k_minmax<<<256, 256>>>(weight, nw);
    k_quant<<<(nw + 255) / 256, 256>>>(weight);
    k_onn_main<<<256, NTH, SMEM_TOTAL>>>(inp, out);
}

// round 6
// speedup vs baseline: 1.4548x; 1.1455x over previous
#include <cuda_runtime.h>
#include <cstdint>

// ---------------- problem constants ----------------
#define CIN   128
#define COUT  256
#define DTOT  1152
#define RCH   18
#define NTH   640            // 512 consumer + 128 producer threads

#define A_STRIDE 68                     // conflict-free for STS & frag LDS
#define A_PLANE  (128 * A_STRIDE)       // 8704
#define B_STRIDE 72
#define B_OFF    (3 * A_PLANE)          // 26112 (planes: hi, mid, lo)
#define STAGE    (B_OFF + 128 * B_STRIDE)  // 35328
#define CTAB_OFF (2 * STAGE)            // 70656
#define BAR_OFF  (CTAB_OFF + DTOT * 4)  // 75264
#define SMEM_TOTAL (BAR_OFF + 64)
// barriers: full[s] at BAR_OFF + s*8 ; empty[s] at BAR_OFF + 16 + s*8

// ---------------- device scratch ----------------
__device__ unsigned g_mm[2];
__device__ __align__(16) signed char g_wq[RCH * COUT * 64]; // s8 W [r][m][k]

// ---------------- helpers ----------------
__device__ __forceinline__ unsigned encf(float f) {
    int b = __float_as_int(f);
    return (b < 0) ? ~(unsigned)b : ((unsigned)b | 0x80000000u);
}
__device__ __forceinline__ float decf(unsigned u) {
    int b = (u & 0x80000000u) ? (int)(u & 0x7fffffffu) : ~(int)u;
    return __int_as_float(b);
}
__device__ __forceinline__ uint32_t smem_u32(const void* p) {
    uint32_t a;
    asm("{ .reg .u64 t; cvta.to.shared.u64 t, %1; cvt.u32.u64 %0, t; }"
        : "=r"(a) : "l"(p));
    return a;
}
__device__ __forceinline__ void imma(int* d, const unsigned* a, const unsigned* b) {
    asm volatile(
        "mma.sync.aligned.m16n8k32.row.col.s32.s8.s8.s32 "
        "{%0,%1,%2,%3}, {%4,%5,%6,%7}, {%8,%9}, {%0,%1,%2,%3};"
        : "+r"(d[0]), "+r"(d[1]), "+r"(d[2]), "+r"(d[3])
        : "r"(a[0]), "r"(a[1]), "r"(a[2]), "r"(a[3]),
          "r"(b[0]), "r"(b[1]));
}

#define MBAR_INIT(a, c) \
    asm volatile("mbarrier.init.shared.b64 [%0], %1;" :: "r"(a), "r"((uint32_t)(c)) : "memory")
#define MBAR_ARRIVE(a) \
    asm volatile("mbarrier.arrive.shared.b64 _, [%0];" :: "r"(a) : "memory")
#define MBAR_WAIT(a, ph) do {                                                   \
    uint32_t _m = (a); uint32_t _p = (ph); uint32_t _d;                         \
    asm volatile("{\n\t.reg .pred p;\n\t"                                       \
        "mbarrier.try_wait.parity.shared.b64 p, [%1], %2;\n\t"                  \
        "selp.b32 %0, 1, 0, p;\n\t}" : "=r"(_d) : "r"(_m), "r"(_p) : "memory"); \
    if (!_d) {                                                                  \
        asm volatile("{\n\t.reg .pred P1;\n\t"                                  \
        "W_%=:\n\t"                                                             \
        "mbarrier.try_wait.parity.shared.b64 P1, [%0], %1;\n\t"                 \
        "@P1 bra.uni D_%=;\n\t"                                                 \
        "bra.uni W_%=;\n\t"                                                     \
        "D_%=:\n\t}" :: "r"(_m), "r"(_p) : "memory");                           \
    }                                                                           \
} while (0)
#define CP_ASYNC8(dst, src) \
    asm volatile("cp.async.ca.shared.global [%0], [%1], 8;" :: "r"(dst), "l"(src))
#define CP_COMMIT() asm volatile("cp.async.commit_group;" ::: "memory")
#define CP_WAIT0()  asm volatile("cp.async.wait_group 0;" ::: "memory")

// ---------------- pre-kernels ----------------
__global__ void k_init_mm() { if (threadIdx.x < 2) g_mm[threadIdx.x] = 0u; }

__global__ void k_minmax(const float* __restrict__ w, int n) {
    unsigned mx = 0u, mn = 0u;
    for (int i = blockIdx.x * blockDim.x + threadIdx.x; i < n;
         i += gridDim.x * blockDim.x) {
        float f = w[i];
        unsigned e0 = encf(f), e1 = encf(-f);
        mx = mx > e0 ? mx : e0;
        mn = mn > e1 ? mn : e1;
    }
    #pragma unroll
    for (int o = 16; o; o >>= 1) {
        unsigned a = __shfl_xor_sync(0xffffffffu, mx, o);
        unsigned b = __shfl_xor_sync(0xffffffffu, mn, o);
        mx = mx > a ? mx : a;
        mn = mn > b ? mn : b;
    }
    if ((threadIdx.x & 31) == 0) {
        atomicMax(&g_mm[0], mx);
        atomicMax(&g_mm[1], mn);
    }
}

__global__ void k_quant(const float* __restrict__ w) {
    int idx = blockIdx.x * blockDim.x + threadIdx.x;
    if (idx >= COUT * DTOT) return;
    float mx = decf(g_mm[0]);
    float mn = -decf(g_mm[1]);
    float scale = 15.0f / (mx - mn + 1e-9f);
    int m = idx / DTOT;
    int d = idx - m * DTOT;
    float q = fminf(fmaxf(rintf(w[idx] * scale), -7.0f), 7.0f);
    int r = d >> 6, kk = d & 63;
    g_wq[(r * COUT + m) * 64 + kk] = (signed char)(int)q;
}

// ---------------- main kernel: warp-specialized, 2 CTAs/SM ----------------
__global__ __launch_bounds__(NTH, 2)
void k_onn_main(const float* __restrict__ inp, float* __restrict__ out) {
    extern __shared__ __align__(16) unsigned char smem[];
    const uint32_t sb = smem_u32(smem);
    const int tid  = threadIdx.x;
    const int lane = tid & 31;

    const int bx = blockIdx.x;
    const int b  = bx >> 4;
    const int pb = (bx >> 1) & 7;
    const int h  = bx & 1;
    const int pixbase = pb * 128;
    const int y0 = pb * 4;
    const int chbase = h * 128;

    const float* __restrict__ inb = inp + (size_t)b * (CIN * 1024);
    int* __restrict__ ctab = (int*)(smem + CTAB_OFF);

    // decode table: d -> (c<<8)|(dy<<4)|dx  (dy,dx in 0..2)
    for (int i = tid; i < DTOT; i += NTH) {
        int c = i / 9, e = i - 9 * c;
        int dy = e / 3, dx = e - 3 * dy;
        ctab[i] = (c << 8) | (dy << 4) | dx;
    }
    if (tid == 0) {
        MBAR_INIT(sb + BAR_OFF + 0, 128);   // full[0]
        MBAR_INIT(sb + BAR_OFF + 8, 128);   // full[1]
        MBAR_INIT(sb + BAR_OFF + 16, 512);  // empty[0]
        MBAR_INIT(sb + BAR_OFF + 24, 512);  // empty[1]
    }
    __syncthreads();

    if (tid < 512) {
        // =================== consumers: 16 warps ===================
        const int wid = tid >> 5;
        const int wm  = wid & 3;
        const int wn  = wid >> 2;
        int phf0 = 0, phf1 = 0;

        unsigned cnt[8];
        #pragma unroll
        for (int t = 0; t < 8; t++) cnt[t] = 0u;

        for (int r = 0; r < RCH; r++) {
            const int s = r & 1;
            MBAR_WAIT(sb + BAR_OFF + s * 8, (s ? phf1 : phf0));
            if (s) phf1 ^= 1; else phf0 ^= 1;

            const unsigned char* As = smem + s * STAGE;
            const unsigned char* Bs = As + B_OFF;

            unsigned bf[4][2][2];
            #pragma unroll
            for (int nt = 0; nt < 4; nt++)
                #pragma unroll
                for (int ks = 0; ks < 2; ks++)
                    #pragma unroll
                    for (int q = 0; q < 2; q++) {
                        const int n = wn * 32 + nt * 8 + (lane >> 2);
                        bf[nt][ks][q] = *(const unsigned*)
                            (Bs + n * B_STRIDE + ks * 32 + q * 16 + (lane & 3) * 4);
                    }

            int acc[8][4];
            #pragma unroll
            for (int t = 0; t < 8; t++)
                #pragma unroll
                for (int q = 0; q < 4; q++) acc[t][q] = 0;

            #pragma unroll
            for (int pl = 0; pl < 2; pl++) {          // hi, mid
                if (pl) {
                    #pragma unroll
                    for (int t = 0; t < 8; t++)
                        #pragma unroll
                        for (int q = 0; q < 4; q++) acc[t][q] <<= 8;
                }
                unsigned af[2][2][4];
                #pragma unroll
                for (int mt = 0; mt < 2; mt++)
                    #pragma unroll
                    for (int ks = 0; ks < 2; ks++)
                        #pragma unroll
                        for (int q = 0; q < 4; q++) {
                            const int row = wm * 32 + mt * 16 + (lane >> 2) + (q & 1) * 8;
                            const int kb  = ks * 32 + (q >> 1) * 16 + (lane & 3) * 4;
                            af[mt][ks][q] = *(const unsigned*)
                                (As + pl * A_PLANE + row * A_STRIDE + kb);
                        }
                #pragma unroll
                for (int mt = 0; mt < 2; mt++)
                    #pragma unroll
                    for (int nt = 0; nt < 4; nt++) {
                        imma(acc[mt * 4 + nt], af[mt][0], bf[nt][0]);
                        imma(acc[mt * 4 + nt], af[mt][1], bf[nt][1]);
                    }
            }

            // ---- binarize + base count; build private candidate mask ----
            unsigned cm = 0u;
            #pragma unroll
            for (int t = 0; t < 8; t++) {
                unsigned inc = 0;
                #pragma unroll
                for (int q = 0; q < 4; q++) {
                    int v = acc[t][q];
                    inc |= ((unsigned)(~v) >> 31) << (8 * q);
                    if ((unsigned)(v + 224) <= 448u) cm |= 1u << (t * 4 + q);
                }
                cnt[t] += inc;
            }

            // ---- exact lo-plane fixup, per-thread (no warp votes) ----
            while (cm) {
                const int i = __ffs(cm) - 1;
                cm &= cm - 1;
                const int t = i >> 2, q = i & 3;
                const int mt = t >> 2, nt = t & 3;
                const int row = wm * 32 + mt * 16 + (lane >> 2) + ((q & 2) ? 8 : 0);
                const int col = wn * 32 + nt * 8 + 2 * (lane & 3) + (q & 1);
                const int* xl = (const int*)(As + 2 * A_PLANE + row * A_STRIDE);
                const int* wc = (const int*)(Bs + col * B_STRIDE);
                int slo = 0;
                #pragma unroll
                for (int kk = 0; kk < 16; kk++)
                    slo = __dp4a(xl[kk], wc[kk], slo);
                const int S = (acc[t][q] << 8) + slo;
                const unsigned ob = (unsigned)(~acc[t][q]) >> 31;
                const unsigned nb = (unsigned)(~S) >> 31;
                cnt[t] += (nb - ob) << (8 * q);   // byte>=1 when subtracting: no borrow
            }
            MBAR_ARRIVE(sb + BAR_OFF + 16 + s * 8);
        }

        // ---- coalesced store via warp shuffle transpose ----
        float* __restrict__ ob =
            out + (size_t)b * (COUT * 1024) + (size_t)chbase * 1024 + pixbase;
        #pragma unroll
        for (int nt = 0; nt < 4; nt++) {
            const unsigned va = cnt[nt];
            const unsigned vb = cnt[4 + nt];
            #pragma unroll
            for (int c8 = 0; c8 < 8; c8++) {
                const int src = ((lane & 7) << 2) + (c8 >> 1);
                unsigned sa = __shfl_sync(0xffffffffu, va, src);
                unsigned sx = __shfl_sync(0xffffffffu, vb, src);
                unsigned v  = (lane & 16) ? sx : sa;
                const int byte = ((lane >> 3) & 1) * 2 + (c8 & 1);
                const float fv = (float)((v >> (byte * 8)) & 255u);
                ob[(size_t)(wn * 32 + nt * 8 + c8) * 1024 + wm * 32 + lane] = fv;
            }
        }
    } else {
        // =================== producers: 4 warps ===================
        const int pp = tid - 512;           // 0..127 = pixel row in tile
        const int py = y0 + (pp >> 5);
        const int px = pp & 31;
        int phe0 = 1, phe1 = 1;

        for (int p = 0; p < RCH; p++) {
            const int s = p & 1;
            MBAR_WAIT(sb + BAR_OFF + 16 + s * 8, (s ? phe1 : phe0));
            if (s) phe1 ^= 1; else phe0 ^= 1;

            unsigned char* Ad = smem + s * STAGE;

            // B tile: 8 x 8B cp.async per thread (row pp)
            {
                const unsigned char* src =
                    (const unsigned char*)g_wq + ((size_t)p * COUT + chbase + pp) * 64;
                const uint32_t dst = sb + s * STAGE + B_OFF + pp * B_STRIDE;
                #pragma unroll
                for (int k8 = 0; k8 < 8; k8++)
                    CP_ASYNC8(dst + k8 * 8, src + k8 * 8);
                CP_COMMIT();
            }

            // A: gather 64 fp32, split to 3 s8 planes; two halves for MLP
            #pragma unroll
            for (int half = 0; half < 2; half++) {
                float v[32];
                #pragma unroll
                for (int i = 0; i < 32; i++) {
                    const int e  = ctab[p * 64 + half * 32 + i];
                    const int yy = py + ((e >> 4) & 15) - 1;
                    const int xx = px + (e & 15) - 1;
                    v[i] = ((unsigned)yy < 32u && (unsigned)xx < 32u)
                             ? inb[((e >> 8) << 10) + yy * 32 + xx] : 0.0f;
                }
                #pragma unroll
                for (int g = 0; g < 8; g++) {
                    unsigned wh = 0, wmd = 0, wl = 0;
                    #pragma unroll
                    for (int j = 0; j < 4; j++) {
                        int vi = __float2int_rn(v[g * 4 + j] * 524288.0f);
                        int lo = (vi << 24) >> 24;
                        int t1 = (vi - lo) >> 8;
                        int mi = (t1 << 24) >> 24;
                        int hi = (t1 - mi) >> 8;
                        wh  |= ((unsigned)hi & 255u) << (8 * j);
                        wmd |= ((unsigned)mi & 255u) << (8 * j);
                        wl  |= ((unsigned)lo & 255u) << (8 * j);
                    }
                    const int off = pp * A_STRIDE + (half * 8 + g) * 4;
                    *(unsigned*)(Ad + off)               = wh;
                    *(unsigned*)(Ad + A_PLANE + off)     = wmd;
                    *(unsigned*)(Ad + 2 * A_PLANE + off) = wl;
                }
            }
            CP_WAIT0();
            MBAR_ARRIVE(sb + BAR_OFF + s * 8);
        }
    }
}

// ---------------- launcher ----------------
extern "C" void kernel_launch(void* const* d_in, const int* in_sizes, int n_in,
                              void* d_out, int out_size) {
    const float* inp    = (const float*)d_in[0];  // [16,128,32,32]
    const float* weight = (const float*)d_in[1];  // [256,128,3,3]
    float* out          = (float*)d_out;          // [16,256,32,32]

    const int nw = COUT * DTOT;

    cudaFuncSetAttribute(k_onn_main,
                         cudaFuncAttributeMaxDynamicSharedMemorySize, SMEM_TOTAL);
    cudaFuncSetAttribute(k_onn_main,
                         cudaFuncAttributePreferredSharedMemoryCarveout, 100);

    k_init_mm<<<1, 32>>>();
    k_minmax<<<256, 256>>>(weight, nw);
    k_quant<<<(nw + 255) / 256, 256>>>(weight);
    k_onn_main<<<256, NTH, SMEM_TOTAL>>>(inp, out);
}